// round 1
// baseline (speedup 1.0000x reference)
#include <cuda_runtime.h>

#define B  4
#define T  1024
#define DM 512
#define NH 8
#define DK 64

// ---------------- scratch (device globals; no allocs allowed) ----------------
__device__ float g_Q[B * NH * T * DK];            // 8 MB
__device__ float g_K[B * NH * T * DK];            // 8 MB
__device__ float g_V[B * NH * T * DK];            // 8 MB
__device__ float g_M[(size_t)B * NH * T * T];     // 128 MB
__device__ float g_Mt[(size_t)B * NH * T * T];    // 128 MB
__device__ float g_Ctx[B * T * DM];               // 8 MB

// ---------------- generic GEMM: C[M x 512] = A[M x 512] @ W[512 x 512]^T -----
// MODE 0: A = g_Ctx, C = param (row-major [row*512+col])  -> output projection
// MODE 1/2/3: A = param, C = g_Q/g_K/g_V in (B,H,T,DK) head-split layout
template <int MODE>
__global__ void __launch_bounds__(256) gemm_xwT(const float* __restrict__ Ain,
                                                const float* __restrict__ W,
                                                float* __restrict__ Cout) {
    __shared__ float As[16][65];
    __shared__ float Ws[16][65];

    const float* A = (MODE == 0) ? (const float*)g_Ctx : Ain;
    float* C;
    if (MODE == 1)      C = g_Q;
    else if (MODE == 2) C = g_K;
    else if (MODE == 3) C = g_V;
    else                C = Cout;

    int tx = threadIdx.x, ty = threadIdx.y;
    int tid = ty * 16 + tx;
    int m0 = blockIdx.y * 64;
    int n0 = blockIdx.x * 64;

    float acc[4][4] = {};

    for (int k0 = 0; k0 < 512; k0 += 16) {
        #pragma unroll
        for (int i = 0; i < 4; i++) {
            int e = tid + i * 256;
            int kk = e & 15, m = e >> 4;
            As[kk][m] = A[(m0 + m) * 512 + k0 + kk];
            Ws[kk][m] = W[(n0 + m) * 512 + k0 + kk];
        }
        __syncthreads();
        #pragma unroll
        for (int kk = 0; kk < 16; kk++) {
            float a[4], w[4];
            #pragma unroll
            for (int i = 0; i < 4; i++) a[i] = As[kk][ty * 4 + i];
            #pragma unroll
            for (int j = 0; j < 4; j++) w[j] = Ws[kk][tx * 4 + j];
            #pragma unroll
            for (int i = 0; i < 4; i++)
                #pragma unroll
                for (int j = 0; j < 4; j++) acc[i][j] += a[i] * w[j];
        }
        __syncthreads();
    }

    #pragma unroll
    for (int i = 0; i < 4; i++) {
        #pragma unroll
        for (int j = 0; j < 4; j++) {
            int row = m0 + ty * 4 + i;
            int col = n0 + tx * 4 + j;
            if (MODE == 0) {
                C[row * 512 + col] = acc[i][j];
            } else {
                int b = row >> 10, t = row & 1023;
                int h = col >> 6,  d = col & 63;
                C[((b * NH + h) * T + t) * DK + d] = acc[i][j];
            }
        }
    }
}

// ---------------- M = Q K^T per (b,h) ----------------------------------------
__global__ void __launch_bounds__(256) qk_kernel() {
    __shared__ float Qs[64][65];
    __shared__ float Ks[64][65];

    int bh = blockIdx.z;
    const float* Qb = g_Q + (size_t)bh * T * DK;
    const float* Kb = g_K + (size_t)bh * T * DK;
    int q0 = blockIdx.y * 64;
    int k0 = blockIdx.x * 64;
    int tx = threadIdx.x, ty = threadIdx.y;
    int tid = ty * 16 + tx;

    #pragma unroll
    for (int i = 0; i < 16; i++) {
        int e = tid + i * 256;
        int d = e & 63, r = e >> 6;
        Qs[d][r] = Qb[(q0 + r) * DK + d];
        Ks[d][r] = Kb[(k0 + r) * DK + d];
    }
    __syncthreads();

    float acc[4][4] = {};
    #pragma unroll
    for (int kk = 0; kk < 64; kk++) {
        float a[4], b[4];
        #pragma unroll
        for (int i = 0; i < 4; i++) a[i] = Qs[kk][ty * 4 + i];
        #pragma unroll
        for (int j = 0; j < 4; j++) b[j] = Ks[kk][tx * 4 + j];
        #pragma unroll
        for (int i = 0; i < 4; i++)
            #pragma unroll
            for (int j = 0; j < 4; j++) acc[i][j] += a[i] * b[j];
    }

    float* Mb = g_M + (size_t)bh * T * T;
    #pragma unroll
    for (int i = 0; i < 4; i++)
        #pragma unroll
        for (int j = 0; j < 4; j++)
            Mb[(size_t)(q0 + ty * 4 + i) * T + (k0 + tx * 4 + j)] = acc[i][j];
}

// ---------------- Mt = conv3x3(prev, tw) + tb  (8 -> 8 channels) -------------
__global__ void __launch_bounds__(1024) conv_mt(const float* __restrict__ prev,
                                                const float* __restrict__ tw,
                                                const float* __restrict__ tb) {
    __shared__ float s[8][34][34];
    __shared__ float sw[8 * 8 * 9];
    __shared__ float stb[8];

    int b = blockIdx.z;
    int tx = threadIdx.x, ty = threadIdx.y;
    int tid = ty * 32 + tx;

    if (tid < 8 * 8 * 9) sw[tid] = tw[tid];
    if (tid < 8) stb[tid] = tb[tid];

    int y0 = blockIdx.y * 32 - 1;
    int x0 = blockIdx.x * 32 - 1;

    for (int e = tid; e < 8 * 34 * 34; e += 1024) {
        int c = e / 1156;
        int r = (e % 1156) / 34;
        int cc = e % 34;
        int y = y0 + r, x = x0 + cc;
        float v = 0.f;
        if (y >= 0 && y < T && x >= 0 && x < T)
            v = prev[((size_t)(b * 8 + c) * T + y) * T + x];
        s[c][r][cc] = v;
    }
    __syncthreads();

    float acc[8];
    #pragma unroll
    for (int o = 0; o < 8; o++) acc[o] = stb[o];

    #pragma unroll
    for (int c = 0; c < 8; c++) {
        float v[9];
        #pragma unroll
        for (int dy = 0; dy < 3; dy++)
            #pragma unroll
            for (int dx = 0; dx < 3; dx++)
                v[dy * 3 + dx] = s[c][ty + dy][tx + dx];
        #pragma unroll
        for (int o = 0; o < 8; o++) {
            const float* wp = &sw[(o * 8 + c) * 9];
            #pragma unroll
            for (int t9 = 0; t9 < 9; t9++) acc[o] += wp[t9] * v[t9];
        }
    }

    int y = y0 + 1 + ty, x = x0 + 1 + tx;
    #pragma unroll
    for (int o = 0; o < 8; o++)
        g_Mt[((size_t)(b * 8 + o) * T + y) * T + x] = acc[o];
}

// ---------------- Apre = (conv3x3(concat(M,Mt), aw) + ab)/8 , masked ---------
__global__ void __launch_bounds__(1024) conv_ma(const float* __restrict__ aw,
                                                const float* __restrict__ ab,
                                                const int* __restrict__ mask,
                                                float* __restrict__ Apre) {
    __shared__ float s[8][34][34];
    __shared__ float sw[8 * 16 * 9];
    __shared__ float sab[8];

    int b = blockIdx.z;
    int tx = threadIdx.x, ty = threadIdx.y;
    int tid = ty * 32 + tx;

    for (int e = tid; e < 8 * 16 * 9; e += 1024) sw[e] = aw[e];
    if (tid < 8) sab[tid] = ab[tid];

    int y0 = blockIdx.y * 32 - 1;
    int x0 = blockIdx.x * 32 - 1;

    float acc[8];

    // ---- pass 0: input channels 0..7 = M ----
    for (int e = tid; e < 8 * 34 * 34; e += 1024) {
        int c = e / 1156;
        int r = (e % 1156) / 34;
        int cc = e % 34;
        int y = y0 + r, x = x0 + cc;
        float v = 0.f;
        if (y >= 0 && y < T && x >= 0 && x < T)
            v = g_M[((size_t)(b * 8 + c) * T + y) * T + x];
        s[c][r][cc] = v;
    }
    __syncthreads();

    #pragma unroll
    for (int o = 0; o < 8; o++) acc[o] = sab[o];

    #pragma unroll
    for (int c = 0; c < 8; c++) {
        float v[9];
        #pragma unroll
        for (int dy = 0; dy < 3; dy++)
            #pragma unroll
            for (int dx = 0; dx < 3; dx++)
                v[dy * 3 + dx] = s[c][ty + dy][tx + dx];
        #pragma unroll
        for (int o = 0; o < 8; o++) {
            const float* wp = &sw[(o * 16 + c) * 9];
            #pragma unroll
            for (int t9 = 0; t9 < 9; t9++) acc[o] += wp[t9] * v[t9];
        }
    }
    __syncthreads();

    // ---- pass 1: input channels 8..15 = Mt ----
    for (int e = tid; e < 8 * 34 * 34; e += 1024) {
        int c = e / 1156;
        int r = (e % 1156) / 34;
        int cc = e % 34;
        int y = y0 + r, x = x0 + cc;
        float v = 0.f;
        if (y >= 0 && y < T && x >= 0 && x < T)
            v = g_Mt[((size_t)(b * 8 + c) * T + y) * T + x];
        s[c][r][cc] = v;
    }
    __syncthreads();

    #pragma unroll
    for (int c = 0; c < 8; c++) {
        float v[9];
        #pragma unroll
        for (int dy = 0; dy < 3; dy++)
            #pragma unroll
            for (int dx = 0; dx < 3; dx++)
                v[dy * 3 + dx] = s[c][ty + dy][tx + dx];
        #pragma unroll
        for (int o = 0; o < 8; o++) {
            const float* wp = &sw[(o * 16 + (c + 8)) * 9];
            #pragma unroll
            for (int t9 = 0; t9 < 9; t9++) acc[o] += wp[t9] * v[t9];
        }
    }

    int y = y0 + 1 + ty, x = x0 + 1 + tx;
    bool masked = (mask[b * T + x] == 0);
    #pragma unroll
    for (int o = 0; o < 8; o++) {
        float r = acc[o] * 0.125f;   // 1/sqrt(DK)
        if (masked) r = -1e9f;
        Apre[((size_t)(b * 8 + o) * T + y) * T + x] = r;
    }
}

// ---------------- in-place row softmax over last dim (rows of length 1024) ---
__global__ void __launch_bounds__(256) softmax_kernel(float* __restrict__ A) {
    __shared__ float red[8];
    int row = blockIdx.x;
    float* p = A + (size_t)row * 1024;
    int tid = threadIdx.x;

    float v[4];
    #pragma unroll
    for (int i = 0; i < 4; i++) v[i] = p[tid + i * 256];

    float mx = fmaxf(fmaxf(v[0], v[1]), fmaxf(v[2], v[3]));
    #pragma unroll
    for (int o = 16; o > 0; o >>= 1) mx = fmaxf(mx, __shfl_xor_sync(~0u, mx, o));
    if ((tid & 31) == 0) red[tid >> 5] = mx;
    __syncthreads();
    mx = red[0];
    #pragma unroll
    for (int i = 1; i < 8; i++) mx = fmaxf(mx, red[i]);
    __syncthreads();

    float s = 0.f;
    #pragma unroll
    for (int i = 0; i < 4; i++) {
        v[i] = __expf(v[i] - mx);
        s += v[i];
    }
    #pragma unroll
    for (int o = 16; o > 0; o >>= 1) s += __shfl_xor_sync(~0u, s, o);
    if ((tid & 31) == 0) red[tid >> 5] = s;
    __syncthreads();
    s = 0.f;
    #pragma unroll
    for (int i = 0; i < 8; i++) s += red[i];
    float inv = 1.f / s;

    #pragma unroll
    for (int i = 0; i < 4; i++) p[tid + i * 256] = v[i] * inv;
}

// ---------------- Ctx = A @ V, written in (B,T,DM) interleaved layout --------
__global__ void __launch_bounds__(256) av_kernel(const float* __restrict__ A) {
    __shared__ float As[32][129];
    __shared__ float Vs[32][64];

    int bh = blockIdx.z;
    int b = bh >> 3, h = bh & 7;
    const float* Ab = A + (size_t)bh * T * T;
    const float* Vb = g_V + (size_t)bh * T * DK;
    int q0 = blockIdx.x * 128;
    int tx = threadIdx.x, ty = threadIdx.y;
    int tid = ty * 16 + tx;

    float acc[8][4] = {};

    for (int kc = 0; kc < T; kc += 32) {
        #pragma unroll
        for (int i = 0; i < 16; i++) {
            int e = tid + i * 256;
            int kk = e & 31, r = e >> 5;
            As[kk][r] = Ab[(size_t)(q0 + r) * T + kc + kk];
        }
        #pragma unroll
        for (int i = 0; i < 8; i++) {
            int e = tid + i * 256;
            int d = e & 63, kk = e >> 6;
            Vs[kk][d] = Vb[(kc + kk) * DK + d];
        }
        __syncthreads();
        #pragma unroll
        for (int kk = 0; kk < 32; kk++) {
            float a[8], vv[4];
            #pragma unroll
            for (int i = 0; i < 8; i++) a[i] = As[kk][ty * 8 + i];
            #pragma unroll
            for (int j = 0; j < 4; j++) vv[j] = Vs[kk][tx * 4 + j];
            #pragma unroll
            for (int i = 0; i < 8; i++)
                #pragma unroll
                for (int j = 0; j < 4; j++) acc[i][j] += a[i] * vv[j];
        }
        __syncthreads();
    }

    #pragma unroll
    for (int i = 0; i < 8; i++) {
        int q = q0 + ty * 8 + i;
        #pragma unroll
        for (int j = 0; j < 4; j++)
            g_Ctx[(size_t)(b * T + q) * DM + h * DK + tx * 4 + j] = acc[i][j];
    }
}

// ---------------- launcher ---------------------------------------------------
extern "C" void kernel_launch(void* const* d_in, const int* in_sizes, int n_in,
                              void* d_out, int out_size) {
    const float* q    = (const float*)d_in[0];
    const float* k    = (const float*)d_in[1];
    const float* v    = (const float*)d_in[2];
    const int*   mask = (const int*)  d_in[3];
    const float* prev = (const float*)d_in[4];
    const float* w_q  = (const float*)d_in[5];
    const float* w_k  = (const float*)d_in[6];
    const float* w_v  = (const float*)d_in[7];
    const float* w_o  = (const float*)d_in[8];
    const float* tw   = (const float*)d_in[9];
    const float* tb   = (const float*)d_in[10];
    const float* aw   = (const float*)d_in[11];
    const float* ab   = (const float*)d_in[12];

    float* out  = (float*)d_out;
    float* Aout = out + (size_t)B * T * DM;   // second tuple element: A

    dim3 tb2(16, 16);
    dim3 gemm_grid(DM / 64, (B * T) / 64);

    // projections -> g_Q, g_K, g_V
    gemm_xwT<1><<<gemm_grid, tb2>>>(q, w_q, nullptr);
    gemm_xwT<2><<<gemm_grid, tb2>>>(k, w_k, nullptr);
    gemm_xwT<3><<<gemm_grid, tb2>>>(v, w_v, nullptr);

    // M = Q K^T
    qk_kernel<<<dim3(T / 64, T / 64, B * NH), tb2>>>();

    // Mt = conv(prev, tw) + tb
    conv_mt<<<dim3(T / 32, T / 32, B), dim3(32, 32)>>>(prev, tw, tb);

    // Apre = (conv(concat(M,Mt), aw) + ab) / 8, masked; written into d_out
    conv_ma<<<dim3(T / 32, T / 32, B), dim3(32, 32)>>>(aw, ab, mask, Aout);

    // softmax in place on A region of d_out
    softmax_kernel<<<B * NH * T, 256>>>(Aout);

    // Ctx = A @ V  (interleaved (B,T,DM) layout)
    av_kernel<<<dim3(T / 128, 1, B * NH), tb2>>>(Aout);

    // out = Ctx @ w_o^T
    gemm_xwT<0><<<gemm_grid, tb2>>>(nullptr, w_o, out);
}

// round 2
// speedup vs baseline: 1.8383x; 1.8383x over previous
#include <cuda_runtime.h>

#define B  4
#define T  1024
#define DM 512
#define NH 8
#define DK 64

// ---------------- scratch (device globals; no allocs allowed) ----------------
__device__ float g_Q[B * NH * T * DK];
__device__ float g_K[B * NH * T * DK];
__device__ float g_V[B * NH * T * DK];
__device__ float g_M[(size_t)B * NH * T * T];
__device__ float g_Mt[(size_t)B * NH * T * T];
__device__ float g_Ctx[B * T * DM];

// packed f32x2 FMA (PTX-only; ptxas never auto-fuses this)
union F2U { float2 f; unsigned long long u; };
__device__ __forceinline__ void ffma2(float2& c, float2 a, float2 b) {
    F2U A, Bv, C;
    A.f = a; Bv.f = b; C.f = c;
    asm("fma.rn.f32x2 %0, %1, %2, %0;" : "+l"(C.u) : "l"(A.u), "l"(Bv.u));
    c = C.f;
}

// =============================================================================
// QKV projections: one launch, z = 0/1/2 selects (q,w_q)->g_Q etc.
// C[m, n] = sum_k A[m,k] * W[n,k];  A: 4096x512, W: 512x512
// 128x64 CTA tile, 32-deep K chunks, 8x4 per thread (f32x2 packed).
// =============================================================================
__global__ void __launch_bounds__(256) gemm_qkv(const float* __restrict__ q,
                                                const float* __restrict__ k,
                                                const float* __restrict__ v,
                                                const float* __restrict__ w_q,
                                                const float* __restrict__ w_k,
                                                const float* __restrict__ w_v) {
    __shared__ float As[32][132];
    __shared__ float Ws[32][68];

    int z = blockIdx.z;
    const float* A = (z == 0) ? q : (z == 1) ? k : v;
    const float* W = (z == 0) ? w_q : (z == 1) ? w_k : w_v;
    float* C = (z == 0) ? g_Q : (z == 1) ? g_K : g_V;

    int m0 = blockIdx.y * 128;
    int n0 = blockIdx.x * 64;
    int tid = threadIdx.x;
    int tx = tid & 15, ty = tid >> 4;
    int rb = tid >> 3, kk = (tid & 7) * 4;

    float2 acc[8][2];
    #pragma unroll
    for (int i = 0; i < 8; i++) { acc[i][0] = make_float2(0.f, 0.f); acc[i][1] = make_float2(0.f, 0.f); }

    for (int k0 = 0; k0 < 512; k0 += 32) {
        #pragma unroll
        for (int i = 0; i < 4; i++) {
            float4 t4 = *(const float4*)&A[(size_t)(m0 + rb + i * 32) * 512 + k0 + kk];
            As[kk + 0][rb + i * 32] = t4.x; As[kk + 1][rb + i * 32] = t4.y;
            As[kk + 2][rb + i * 32] = t4.z; As[kk + 3][rb + i * 32] = t4.w;
        }
        #pragma unroll
        for (int i = 0; i < 2; i++) {
            float4 t4 = *(const float4*)&W[(size_t)(n0 + rb + i * 32) * 512 + k0 + kk];
            Ws[kk + 0][rb + i * 32] = t4.x; Ws[kk + 1][rb + i * 32] = t4.y;
            Ws[kk + 2][rb + i * 32] = t4.z; Ws[kk + 3][rb + i * 32] = t4.w;
        }
        __syncthreads();
        #pragma unroll
        for (int kx = 0; kx < 32; kx++) {
            float4 a0 = *(float4*)&As[kx][ty * 8];
            float4 a1 = *(float4*)&As[kx][ty * 8 + 4];
            float4 b4 = *(float4*)&Ws[kx][tx * 4];
            float2 b0 = make_float2(b4.x, b4.y), b1 = make_float2(b4.z, b4.w);
            float av[8] = {a0.x, a0.y, a0.z, a0.w, a1.x, a1.y, a1.z, a1.w};
            #pragma unroll
            for (int i = 0; i < 8; i++) {
                float2 ad = make_float2(av[i], av[i]);
                ffma2(acc[i][0], ad, b0);
                ffma2(acc[i][1], ad, b1);
            }
        }
        __syncthreads();
    }

    int h = n0 >> 6;  // 64-wide n-tiles align exactly with heads
    #pragma unroll
    for (int i = 0; i < 8; i++) {
        int row = m0 + ty * 8 + i;
        int b = row >> 10, t = row & 1023;
        float4 o = make_float4(acc[i][0].x, acc[i][0].y, acc[i][1].x, acc[i][1].y);
        *(float4*)&C[(size_t)((b * NH + h) * T + t) * DK + tx * 4] = o;
    }
}

// =============================================================================
// Output projection: out = g_Ctx @ w_o^T
// =============================================================================
__global__ void __launch_bounds__(256) gemm_wo(const float* __restrict__ W,
                                               float* __restrict__ out) {
    __shared__ float As[32][132];
    __shared__ float Ws[32][68];

    int m0 = blockIdx.y * 128;
    int n0 = blockIdx.x * 64;
    int tid = threadIdx.x;
    int tx = tid & 15, ty = tid >> 4;
    int rb = tid >> 3, kk = (tid & 7) * 4;

    float2 acc[8][2];
    #pragma unroll
    for (int i = 0; i < 8; i++) { acc[i][0] = make_float2(0.f, 0.f); acc[i][1] = make_float2(0.f, 0.f); }

    for (int k0 = 0; k0 < 512; k0 += 32) {
        #pragma unroll
        for (int i = 0; i < 4; i++) {
            float4 t4 = *(const float4*)&g_Ctx[(size_t)(m0 + rb + i * 32) * 512 + k0 + kk];
            As[kk + 0][rb + i * 32] = t4.x; As[kk + 1][rb + i * 32] = t4.y;
            As[kk + 2][rb + i * 32] = t4.z; As[kk + 3][rb + i * 32] = t4.w;
        }
        #pragma unroll
        for (int i = 0; i < 2; i++) {
            float4 t4 = *(const float4*)&W[(size_t)(n0 + rb + i * 32) * 512 + k0 + kk];
            Ws[kk + 0][rb + i * 32] = t4.x; Ws[kk + 1][rb + i * 32] = t4.y;
            Ws[kk + 2][rb + i * 32] = t4.z; Ws[kk + 3][rb + i * 32] = t4.w;
        }
        __syncthreads();
        #pragma unroll
        for (int kx = 0; kx < 32; kx++) {
            float4 a0 = *(float4*)&As[kx][ty * 8];
            float4 a1 = *(float4*)&As[kx][ty * 8 + 4];
            float4 b4 = *(float4*)&Ws[kx][tx * 4];
            float2 b0 = make_float2(b4.x, b4.y), b1 = make_float2(b4.z, b4.w);
            float av[8] = {a0.x, a0.y, a0.z, a0.w, a1.x, a1.y, a1.z, a1.w};
            #pragma unroll
            for (int i = 0; i < 8; i++) {
                float2 ad = make_float2(av[i], av[i]);
                ffma2(acc[i][0], ad, b0);
                ffma2(acc[i][1], ad, b1);
            }
        }
        __syncthreads();
    }

    #pragma unroll
    for (int i = 0; i < 8; i++) {
        int row = m0 + ty * 8 + i;
        float4 o = make_float4(acc[i][0].x, acc[i][0].y, acc[i][1].x, acc[i][1].y);
        *(float4*)&out[(size_t)row * 512 + n0 + tx * 4] = o;
    }
}

// =============================================================================
// M = Q K^T per (b,h).  128x64 tile, DK=64 in two 32-chunks.
// =============================================================================
__global__ void __launch_bounds__(256) qk_kernel() {
    __shared__ float Qs[32][132];
    __shared__ float Ks[32][68];

    int bh = blockIdx.z;
    const float* Qb = g_Q + (size_t)bh * T * DK;
    const float* Kb = g_K + (size_t)bh * T * DK;
    int q0 = blockIdx.y * 128;
    int k0 = blockIdx.x * 64;
    int tid = threadIdx.x;
    int tx = tid & 15, ty = tid >> 4;
    int rb = tid >> 3, kk = (tid & 7) * 4;

    float2 acc[8][2];
    #pragma unroll
    for (int i = 0; i < 8; i++) { acc[i][0] = make_float2(0.f, 0.f); acc[i][1] = make_float2(0.f, 0.f); }

    for (int d0 = 0; d0 < 64; d0 += 32) {
        #pragma unroll
        for (int i = 0; i < 4; i++) {
            float4 t4 = *(const float4*)&Qb[(size_t)(q0 + rb + i * 32) * DK + d0 + kk];
            Qs[kk + 0][rb + i * 32] = t4.x; Qs[kk + 1][rb + i * 32] = t4.y;
            Qs[kk + 2][rb + i * 32] = t4.z; Qs[kk + 3][rb + i * 32] = t4.w;
        }
        #pragma unroll
        for (int i = 0; i < 2; i++) {
            float4 t4 = *(const float4*)&Kb[(size_t)(k0 + rb + i * 32) * DK + d0 + kk];
            Ks[kk + 0][rb + i * 32] = t4.x; Ks[kk + 1][rb + i * 32] = t4.y;
            Ks[kk + 2][rb + i * 32] = t4.z; Ks[kk + 3][rb + i * 32] = t4.w;
        }
        __syncthreads();
        #pragma unroll
        for (int kx = 0; kx < 32; kx++) {
            float4 a0 = *(float4*)&Qs[kx][ty * 8];
            float4 a1 = *(float4*)&Qs[kx][ty * 8 + 4];
            float4 b4 = *(float4*)&Ks[kx][tx * 4];
            float2 b0 = make_float2(b4.x, b4.y), b1 = make_float2(b4.z, b4.w);
            float av[8] = {a0.x, a0.y, a0.z, a0.w, a1.x, a1.y, a1.z, a1.w};
            #pragma unroll
            for (int i = 0; i < 8; i++) {
                float2 ad = make_float2(av[i], av[i]);
                ffma2(acc[i][0], ad, b0);
                ffma2(acc[i][1], ad, b1);
            }
        }
        __syncthreads();
    }

    float* Mb = g_M + (size_t)bh * T * T;
    #pragma unroll
    for (int i = 0; i < 8; i++) {
        float4 o = make_float4(acc[i][0].x, acc[i][0].y, acc[i][1].x, acc[i][1].y);
        *(float4*)&Mb[(size_t)(q0 + ty * 8 + i) * T + k0 + tx * 4] = o;
    }
}

// =============================================================================
// Mt = conv3x3(prev, tw) + tb  (8 -> 8 ch). 64x16 output tile, 4 px/thread.
// =============================================================================
__global__ void __launch_bounds__(256) conv_mt(const float* __restrict__ prev,
                                               const float* __restrict__ tw,
                                               const float* __restrict__ tb) {
    __shared__ float s[8][18][66];
    __shared__ float swt[8][9][8];   // [c][t9][o]
    __shared__ float sb[8];

    int b = blockIdx.z;
    int x0 = blockIdx.x * 64;
    int y0 = blockIdx.y * 16;
    int tid = threadIdx.x;
    int tx = tid & 15, ty = tid >> 4;

    for (int e = tid; e < 576; e += 256) {
        int o = e / 72, c = (e % 72) / 9, t9 = e % 9;
        swt[c][t9][o] = tw[e];
    }
    if (tid < 8) sb[tid] = tb[tid];

    for (int e = tid; e < 8 * 18 * 66; e += 256) {
        int c = e / 1188, r = (e % 1188) / 66, cc = e % 66;
        int y = y0 - 1 + r, x = x0 - 1 + cc;
        float val = 0.f;
        if (y >= 0 && y < T && x >= 0 && x < T)
            val = prev[((size_t)(b * 8 + c) * T + y) * T + x];
        s[c][r][cc] = val;
    }
    __syncthreads();

    float2 acc[4][4];
    #pragma unroll
    for (int p = 0; p < 4; p++)
        #pragma unroll
        for (int o2 = 0; o2 < 4; o2++)
            acc[p][o2] = make_float2(sb[o2 * 2], sb[o2 * 2 + 1]);

    int cx = tx * 4;
    #pragma unroll
    for (int c = 0; c < 8; c++) {
        float v[3][6];
        #pragma unroll
        for (int dy = 0; dy < 3; dy++)
            #pragma unroll
            for (int j = 0; j < 6; j++)
                v[dy][j] = s[c][ty + dy][cx + j];
        #pragma unroll
        for (int dy = 0; dy < 3; dy++) {
            #pragma unroll
            for (int dx = 0; dx < 3; dx++) {
                int t9 = dy * 3 + dx;
                float2 w0 = *(float2*)&swt[c][t9][0];
                float2 w1 = *(float2*)&swt[c][t9][2];
                float2 w2 = *(float2*)&swt[c][t9][4];
                float2 w3 = *(float2*)&swt[c][t9][6];
                #pragma unroll
                for (int p = 0; p < 4; p++) {
                    float vv = v[dy][dx + p];
                    float2 vd = make_float2(vv, vv);
                    ffma2(acc[p][0], vd, w0);
                    ffma2(acc[p][1], vd, w1);
                    ffma2(acc[p][2], vd, w2);
                    ffma2(acc[p][3], vd, w3);
                }
            }
        }
    }

    int y = y0 + ty;
    #pragma unroll
    for (int o = 0; o < 8; o++) {
        int o2 = o >> 1;
        float4 ov;
        if (o & 1) ov = make_float4(acc[0][o2].y, acc[1][o2].y, acc[2][o2].y, acc[3][o2].y);
        else       ov = make_float4(acc[0][o2].x, acc[1][o2].x, acc[2][o2].x, acc[3][o2].x);
        *(float4*)&g_Mt[((size_t)(b * 8 + o) * T + y) * T + x0 + cx] = ov;
    }
}

// =============================================================================
// Apre = (conv3x3(concat(M, Mt), aw) + ab) / 8, masked. Writes A into d_out.
// =============================================================================
__global__ void __launch_bounds__(256) conv_ma(const float* __restrict__ aw,
                                               const float* __restrict__ ab,
                                               const int* __restrict__ mask,
                                               float* __restrict__ Apre) {
    __shared__ float s[8][18][66];
    __shared__ float swa[16][9][8];  // [c][t9][o]
    __shared__ float sab[8];

    int b = blockIdx.z;
    int x0 = blockIdx.x * 64;
    int y0 = blockIdx.y * 16;
    int tid = threadIdx.x;
    int tx = tid & 15, ty = tid >> 4;

    for (int e = tid; e < 1152; e += 256) {
        int o = e / 144, c = (e % 144) / 9, t9 = e % 9;
        swa[c][t9][o] = aw[e];
    }
    if (tid < 8) sab[tid] = ab[tid];

    float2 acc[4][4];
    #pragma unroll
    for (int p = 0; p < 4; p++)
        #pragma unroll
        for (int o2 = 0; o2 < 4; o2++)
            acc[p][o2] = make_float2(0.f, 0.f);

    int cx = tx * 4;

    #pragma unroll
    for (int pass = 0; pass < 2; pass++) {
        const float* src = pass ? g_Mt : g_M;
        for (int e = tid; e < 8 * 18 * 66; e += 256) {
            int c = e / 1188, r = (e % 1188) / 66, cc = e % 66;
            int y = y0 - 1 + r, x = x0 - 1 + cc;
            float val = 0.f;
            if (y >= 0 && y < T && x >= 0 && x < T)
                val = src[((size_t)(b * 8 + c) * T + y) * T + x];
            s[c][r][cc] = val;
        }
        __syncthreads();

        #pragma unroll
        for (int c = 0; c < 8; c++) {
            int cw = c + pass * 8;
            float v[3][6];
            #pragma unroll
            for (int dy = 0; dy < 3; dy++)
                #pragma unroll
                for (int j = 0; j < 6; j++)
                    v[dy][j] = s[c][ty + dy][cx + j];
            #pragma unroll
            for (int dy = 0; dy < 3; dy++) {
                #pragma unroll
                for (int dx = 0; dx < 3; dx++) {
                    int t9 = dy * 3 + dx;
                    float2 w0 = *(float2*)&swa[cw][t9][0];
                    float2 w1 = *(float2*)&swa[cw][t9][2];
                    float2 w2 = *(float2*)&swa[cw][t9][4];
                    float2 w3 = *(float2*)&swa[cw][t9][6];
                    #pragma unroll
                    for (int p = 0; p < 4; p++) {
                        float vv = v[dy][dx + p];
                        float2 vd = make_float2(vv, vv);
                        ffma2(acc[p][0], vd, w0);
                        ffma2(acc[p][1], vd, w1);
                        ffma2(acc[p][2], vd, w2);
                        ffma2(acc[p][3], vd, w3);
                    }
                }
            }
        }
        __syncthreads();
    }

    int y = y0 + ty;
    int xg = x0 + cx;
    bool mk[4];
    #pragma unroll
    for (int p = 0; p < 4; p++) mk[p] = (mask[b * T + xg + p] == 0);

    #pragma unroll
    for (int o = 0; o < 8; o++) {
        int o2 = o >> 1;
        float r0, r1, r2, r3;
        if (o & 1) { r0 = acc[0][o2].y; r1 = acc[1][o2].y; r2 = acc[2][o2].y; r3 = acc[3][o2].y; }
        else       { r0 = acc[0][o2].x; r1 = acc[1][o2].x; r2 = acc[2][o2].x; r3 = acc[3][o2].x; }
        float bias = sab[o];
        r0 = (r0 + bias) * 0.125f; r1 = (r1 + bias) * 0.125f;
        r2 = (r2 + bias) * 0.125f; r3 = (r3 + bias) * 0.125f;
        if (mk[0]) r0 = -1e9f;
        if (mk[1]) r1 = -1e9f;
        if (mk[2]) r2 = -1e9f;
        if (mk[3]) r3 = -1e9f;
        float4 ov = make_float4(r0, r1, r2, r3);
        *(float4*)&Apre[((size_t)(b * 8 + o) * T + y) * T + xg] = ov;
    }
}

// ---------------- in-place row softmax (rows of 1024) ------------------------
__global__ void __launch_bounds__(256) softmax_kernel(float* __restrict__ A) {
    __shared__ float red[8];
    int row = blockIdx.x;
    float* p = A + (size_t)row * 1024;
    int tid = threadIdx.x;

    float4 v = *(float4*)&p[tid * 4];

    float mx = fmaxf(fmaxf(v.x, v.y), fmaxf(v.z, v.w));
    #pragma unroll
    for (int o = 16; o > 0; o >>= 1) mx = fmaxf(mx, __shfl_xor_sync(~0u, mx, o));
    if ((tid & 31) == 0) red[tid >> 5] = mx;
    __syncthreads();
    mx = red[0];
    #pragma unroll
    for (int i = 1; i < 8; i++) mx = fmaxf(mx, red[i]);
    __syncthreads();

    v.x = __expf(v.x - mx); v.y = __expf(v.y - mx);
    v.z = __expf(v.z - mx); v.w = __expf(v.w - mx);
    float s = v.x + v.y + v.z + v.w;
    #pragma unroll
    for (int o = 16; o > 0; o >>= 1) s += __shfl_xor_sync(~0u, s, o);
    if ((tid & 31) == 0) red[tid >> 5] = s;
    __syncthreads();
    s = 0.f;
    #pragma unroll
    for (int i = 0; i < 8; i++) s += red[i];
    float inv = 1.f / s;

    v.x *= inv; v.y *= inv; v.z *= inv; v.w *= inv;
    *(float4*)&p[tid * 4] = v;
}

// =============================================================================
// Ctx = A @ V per (b,h). 128x64 tile, K-chunks of 32 over 1024.
// =============================================================================
__global__ void __launch_bounds__(256) av_kernel(const float* __restrict__ A) {
    __shared__ float As[32][132];
    __shared__ float Vs[32][68];

    int bh = blockIdx.y;
    int b = bh >> 3, h = bh & 7;
    const float* Ab = A + (size_t)bh * T * T;
    const float* Vb = g_V + (size_t)bh * T * DK;
    int q0 = blockIdx.x * 128;
    int tid = threadIdx.x;
    int tx = tid & 15, ty = tid >> 4;
    int rb = tid >> 3, kk = (tid & 7) * 4;
    int vd = (tid & 15) * 4, vk = tid >> 4;

    float2 acc[8][2];
    #pragma unroll
    for (int i = 0; i < 8; i++) { acc[i][0] = make_float2(0.f, 0.f); acc[i][1] = make_float2(0.f, 0.f); }

    for (int kc = 0; kc < T; kc += 32) {
        #pragma unroll
        for (int i = 0; i < 4; i++) {
            float4 t4 = *(const float4*)&Ab[(size_t)(q0 + rb + i * 32) * T + kc + kk];
            As[kk + 0][rb + i * 32] = t4.x; As[kk + 1][rb + i * 32] = t4.y;
            As[kk + 2][rb + i * 32] = t4.z; As[kk + 3][rb + i * 32] = t4.w;
        }
        #pragma unroll
        for (int i = 0; i < 2; i++) {
            float4 t4 = *(const float4*)&Vb[(size_t)(kc + vk + i * 16) * DK + vd];
            *(float4*)&Vs[vk + i * 16][vd] = t4;
        }
        __syncthreads();
        #pragma unroll
        for (int kx = 0; kx < 32; kx++) {
            float4 a0 = *(float4*)&As[kx][ty * 8];
            float4 a1 = *(float4*)&As[kx][ty * 8 + 4];
            float4 b4 = *(float4*)&Vs[kx][tx * 4];
            float2 b0 = make_float2(b4.x, b4.y), b1 = make_float2(b4.z, b4.w);
            float av[8] = {a0.x, a0.y, a0.z, a0.w, a1.x, a1.y, a1.z, a1.w};
            #pragma unroll
            for (int i = 0; i < 8; i++) {
                float2 ad = make_float2(av[i], av[i]);
                ffma2(acc[i][0], ad, b0);
                ffma2(acc[i][1], ad, b1);
            }
        }
        __syncthreads();
    }

    #pragma unroll
    for (int i = 0; i < 8; i++) {
        int qrow = q0 + ty * 8 + i;
        float4 o = make_float4(acc[i][0].x, acc[i][0].y, acc[i][1].x, acc[i][1].y);
        *(float4*)&g_Ctx[(size_t)(b * T + qrow) * DM + h * DK + tx * 4] = o;
    }
}

// ---------------- launcher ---------------------------------------------------
extern "C" void kernel_launch(void* const* d_in, const int* in_sizes, int n_in,
                              void* d_out, int out_size) {
    const float* q    = (const float*)d_in[0];
    const float* k    = (const float*)d_in[1];
    const float* v    = (const float*)d_in[2];
    const int*   mask = (const int*)  d_in[3];
    const float* prev = (const float*)d_in[4];
    const float* w_q  = (const float*)d_in[5];
    const float* w_k  = (const float*)d_in[6];
    const float* w_v  = (const float*)d_in[7];
    const float* w_o  = (const float*)d_in[8];
    const float* tw   = (const float*)d_in[9];
    const float* tb   = (const float*)d_in[10];
    const float* aw   = (const float*)d_in[11];
    const float* ab   = (const float*)d_in[12];

    float* out  = (float*)d_out;
    float* Aout = out + (size_t)B * T * DM;

    // projections (fused 3-way launch)
    gemm_qkv<<<dim3(DM / 64, (B * T) / 128, 3), 256>>>(q, k, v, w_q, w_k, w_v);

    // M = Q K^T
    qk_kernel<<<dim3(T / 64, T / 128, B * NH), 256>>>();

    // Mt = conv(prev)
    conv_mt<<<dim3(T / 64, T / 16, B), 256>>>(prev, tw, tb);

    // Apre (scaled, masked) -> d_out A region
    conv_ma<<<dim3(T / 64, T / 16, B), 256>>>(aw, ab, mask, Aout);

    // softmax in place
    softmax_kernel<<<B * NH * T, 256>>>(Aout);

    // Ctx = A @ V
    av_kernel<<<dim3(T / 128, B * NH), 256>>>(Aout);

    // out = Ctx @ w_o^T
    gemm_wo<<<dim3(DM / 64, (B * T) / 128), 256>>>(w_o, out);
}